// round 16
// baseline (speedup 1.0000x reference)
#include <cuda_runtime.h>

// Problem constants
#define NB   4096
#define DIN  1856
#define HH   128
#define WB2  96        // truncated half-width (window covers >= +-96 per row)
#define BSTR 384       // band row stride (t = d+191)
#define GRID 128       // persistent blocks, all co-resident
#define RPB  32        // rows per block
#define CH   48        // matvec chunk rows
#define NCH  5         // 5*48 = 240 window cols
#define NJW  (NCH*CH)  // 240
#define SA   36        // transposed-activation stride
#define NT   512       // threads per block

typedef unsigned long long ull;

// Persistent device scratch (zero-initialized at module load)
__device__ float g_band[NB * BSTR];
__device__ float g_h[NB * HH];
__device__ float g_ybuf[2][NB * HH];
__device__ int g_done[GRID * 32];     // per-block stage flags, 128B-padded

// ---------------------------------------------------------------------------
// f32x2 packed-math helpers
// ---------------------------------------------------------------------------
__device__ __forceinline__ ull dup2(float x) {
    ull r; asm("mov.b64 %0, {%1, %1};" : "=l"(r) : "f"(x)); return r;
}
__device__ __forceinline__ void ffma2(ull& d, ull a, ull b) {
    asm("fma.rn.f32x2 %0, %1, %2, %0;" : "+l"(d) : "l"(a), "l"(b));
}
__device__ __forceinline__ float2 unpk(ull v) {
    float2 f; asm("mov.b64 {%0, %1}, %2;" : "=f"(f.x), "=f"(f.y) : "l"(v));
    return f;
}
__device__ __forceinline__ int ld_acq(const int* p) {
    int v; asm volatile("ld.acquire.gpu.u32 %0, [%1];" : "=r"(v) : "l"(p));
    return v;
}

// 4 rows x 2 cols microtile: 1 LDS.128 (row pairs, broadcast) + 1 LDS.64.
__device__ __forceinline__ void step4(ull acc[2][2],
                                      const float* __restrict__ aBase,
                                      const float* __restrict__ bBase)
{
    ulonglong2 a = *(const ulonglong2*)(aBase);        // rows (0,1),(2,3)
    float2 wv = *(const float2*)(bBase);
    ull w0 = dup2(wv.x), w1 = dup2(wv.y);
    ffma2(acc[0][0], a.x, w0); ffma2(acc[0][1], a.x, w1);
    ffma2(acc[1][0], a.y, w0); ffma2(acc[1][1], a.y, w1);
}

// ---------------------------------------------------------------------------
// Kernel 1: build normalized band adjacency (coalesced layout).
// ---------------------------------------------------------------------------
__global__ void __launch_bounds__(384) build_band_kernel(
    const int* __restrict__ spk, const float* __restrict__ mmask)
{
    int i = blockIdx.x;
    int t = threadIdx.x;            // 0..383, d = t - 191
    int d = t - 191;
    int j = i + d;

    float val = 0.0f;
    bool valid = (t < 383 && j >= 0 && j < NB);
    if (valid) {
        if (d == 0) {
            val = 1.0f;
        } else {
            float temporal = expf(-0.1f * fabsf((float)d));
            if (spk[i] == spk[j]) {
                val = 0.8f * temporal;
            } else {
                float md = fabsf(mmask[i*3+0] - mmask[j*3+0])
                         + fabsf(mmask[i*3+1] - mmask[j*3+1])
                         + fabsf(mmask[i*3+2] - mmask[j*3+2]);
                float mod_sim = 1.0f - md * (1.0f/3.0f);
                val = 0.5f * temporal * mod_sim;
            }
        }
    }

    __shared__ float sd[384];
    sd[t] = val;
    __syncthreads();
    if (t < 128) sd[t] += sd[t + 256];
    __syncthreads();
    for (int s = 128; s > 0; s >>= 1) {
        if (t < s) sd[t] += sd[t + s];
        __syncthreads();
    }
    float inv = 1.0f / (sd[0] + 1e-8f);
    g_band[i * BSTR + t] = val * inv;
}

// ---------------------------------------------------------------------------
// Kernel 2: projection h0 = X @ Wp + bp.  Also resets g_done for this launch.
// ---------------------------------------------------------------------------
__global__ void __launch_bounds__(NT) proj_kernel(
    const float* __restrict__ X, const float* __restrict__ Wp,
    const float* __restrict__ bp)
{
    if (threadIdx.x == 0) g_done[blockIdx.x * 32] = 0;    // flag reset

    __shared__ __align__(16) float As[32 * SA];
    __shared__ __align__(16) float Bs[32 * 128];
    const int m0  = blockIdx.x * RPB;
    const int tid = threadIdx.x;
    const int rg  = tid >> 6;        // rows 4rg..4rg+3 (warp-uniform)
    const int cg  = tid & 63;        // cols 2cg, 2cg+1

    ull acc[2][2];
    acc[0][0]=acc[0][1]=acc[1][0]=acc[1][1]=0ull;

    const int ar  = tid >> 4;        // 0..31
    const int ak2 = (tid & 15) * 2;  // 0..30

    for (int k0 = 0; k0 < DIN; k0 += 32) {
        {
            float2 v = *(const float2*)&X[(m0 + ar) * DIN + k0 + ak2];
            As[(ak2+0)*SA + ar] = v.x;
            As[(ak2+1)*SA + ar] = v.y;
        }
#pragma unroll
        for (int i = tid; i < 1024; i += NT) {
            int k = i >> 5, c4 = (i & 31) * 4;
            *(float4*)&Bs[k*128 + c4] = *(const float4*)&Wp[(k0 + k) * HH + c4];
        }
        __syncthreads();
#pragma unroll 8
        for (int k = 0; k < 32; k++)
            step4(acc, &As[k*SA + 4*rg], &Bs[k*128 + 2*cg]);
        __syncthreads();
    }

    float2 bb = *(const float2*)&bp[2*cg];
#pragma unroll
    for (int q = 0; q < 2; q++) {
        float2 f0 = unpk(acc[q][0]);
        float2 f1 = unpk(acc[q][1]);
        int r_even = m0 + 4*rg + 2*q;
        float2 o0 = make_float2(f0.x + bb.x, f1.x + bb.y);
        float2 o1 = make_float2(f0.y + bb.x, f1.y + bb.y);
        *(float2*)&g_h[r_even * HH + 2*cg]           = o0;
        *(float2*)&g_ybuf[0][r_even * HH + 2*cg]     = o0;
        *(float2*)&g_h[(r_even+1) * HH + 2*cg]       = o1;
        *(float2*)&g_ybuf[0][(r_even+1) * HH + 2*cg] = o1;
    }
}

// ---------------------------------------------------------------------------
// Kernel 3: persistent ODE kernel.
// Band + W1 resident in smem. Per-chunk producer polls (overlap waits with
// compute). W2 staged through smem chunks (sY1 halves). Publish-ASAP flags.
// ---------------------------------------------------------------------------
#define SW1_FLOATS (256 * 128)             // 32768
#define SY_FLOATS  (CH * 128)              // 6144
#define SBT_FLOATS (NJW * 32)              // 7680
#define SYT_FLOATS (128 * SA)              // 4608
#define SMEM_FLOATS (SW1_FLOATS + 2*SY_FLOATS + SBT_FLOATS + SYT_FLOATS)
#define SMEM_BYTES  (SMEM_FLOATS * 4)      // 229376 B

__global__ void __launch_bounds__(NT, 1) ode_kernel(
    const float* __restrict__ W1, const float* __restrict__ b1,
    const float* __restrict__ W2, const float* __restrict__ b2,
    float* __restrict__ outp)
{
    extern __shared__ __align__(16) float smem[];
    float* sW1 = smem;                     // [256][128]
    float* sY0 = sW1 + SW1_FLOATS;         // [CH][128] matvec buffer 0
    float* sY1 = sY0 + SY_FLOATS;          // [CH][128] matvec buffer 1 / W2 halves
    float* sBT = sY1 + SY_FLOATS;          // [NJW][32] resident band slice
    float* sYT = sBT + SBT_FLOATS;         // [128][SA] y^T own rows (persistent)
    float* sAt = sY0;                      // [128][SA] hn^T / z^T (aliases sY0)
    float* sW2h0 = sY1;                    // W2 chunk half 0 (16k x 128 = 8KB)
    float* sW2h1 = sY1 + 2048;             // W2 chunk half 1

    const int tid = threadIdx.x;
    const int rg  = tid >> 6;              // warp-uniform, rows 4rg..4rg+3
    const int cg  = tid & 63;              // cols 2cg, 2cg+1
    const int r0  = blockIdx.x * RPB;
    const int jbase = r0 - WB2;

    // one-time staging: W1, band slice (transposed [jj][r]), y0^T
#pragma unroll
    for (int i = tid; i < SW1_FLOATS/4; i += NT)
        *(float4*)&sW1[i*4] = *(const float4*)&W1[i*4];
#pragma unroll
    for (int i = tid; i < SBT_FLOATS; i += NT) {
        int jj = i >> 5, r = i & 31;
        int gj = jbase + jj;
        float bv = 0.0f;
        if ((unsigned)gj < (unsigned)NB) {
            int dd = jj + 95 - r;          // in [64, 334] always
            bv = g_band[(r0 + r) * BSTR + dd];
        }
        sBT[i] = bv;
    }
#pragma unroll
    for (int i = tid; i < 4096; i += NT) {
        int r = i >> 7, c = i & 127;
        sYT[c*SA + r] = g_ybuf[0][(r0 + r) * HH + c];
    }

    // persistent register state
    float hreg[4][2], rk[4][2];
#pragma unroll
    for (int i = 0; i < 4; i++) {
        float2 v = *(const float2*)&g_h[(r0 + 4*rg + i) * HH + 2*cg];
        hreg[i][0] = v.x; hreg[i][1] = v.y;
    }
    float2 b1v = *(const float2*)&b1[2*cg];
    float2 b2v = *(const float2*)&b2[2*cg];
    const float dt = 0.25f;

    // W2 stage-load geometry: thread covers (k = tid>>5, col4 = (tid&31)*4)
    const int w2k = tid >> 5;
    const int w2c = (tid & 31) * 4;
    __syncthreads();

#pragma unroll 1
    for (int st = 0; st < 16; st++) {
        const int s = st & 3;
        const float* __restrict__ yin  = g_ybuf[st & 1];
        float* __restrict__       yout = g_ybuf[(st + 1) & 1];

        // ---- banded matvec: per-chunk producer polls + double buffering ----
        ull macc[2][2];
        macc[0][0]=macc[0][1]=macc[1][0]=macc[1][1]=0ull;

        float4 py[3];

        // chunk 0: poll producers, prefetch, commit to sY0
        {
#pragma unroll
            for (int q = 0; q < 3; q++) {
                int i = tid + q*NT;
                int row = i >> 5, c4 = (i & 31) * 4;
                int gj = jbase + row;
                py[q] = make_float4(0.f,0.f,0.f,0.f);
                if ((unsigned)gj < (unsigned)NB) {
                    if (st > 0) {
                        const int* fp = &g_done[(gj >> 5) << 5];
                        while (ld_acq(fp) < st) { }
                    }
                    py[q] = __ldcg((const float4*)&yin[gj * HH + c4]);
                }
                *(float4*)&sY0[row * 128 + c4] = py[q];
            }
        }

#pragma unroll 1
        for (int ch = 0; ch < NCH; ch++) {
            __syncthreads();               // current buffer ready
            const float* cY = (ch & 1) ? sY1 : sY0;
            float* nY = (ch & 1) ? sY0 : sY1;
            const float* cB = &sBT[ch * CH * 32];

            // poll + issue next chunk's y loads (overlapped with compute)
            if (ch + 1 < NCH) {
                const int j0 = jbase + (ch + 1) * CH;
#pragma unroll
                for (int q = 0; q < 3; q++) {
                    int i = tid + q*NT;
                    int row = i >> 5, c4 = (i & 31) * 4;
                    int gj = j0 + row;
                    py[q] = make_float4(0.f,0.f,0.f,0.f);
                    if ((unsigned)gj < (unsigned)NB) {
                        if (st > 0) {
                            const int* fp = &g_done[(gj >> 5) << 5];
                            while (ld_acq(fp) < st) { }
                        }
                        py[q] = __ldcg((const float4*)&yin[gj * HH + c4]);
                    }
                }
            }

#pragma unroll 8
            for (int j = 0; j < CH; j++)
                step4(macc, &cB[j*32 + 4*rg], &cY[j*128 + 2*cg]);

            if (ch + 1 < NCH) {
#pragma unroll
                for (int q = 0; q < 3; q++) {
                    int i = tid + q*NT;
                    int row = i >> 5, c4 = (i & 31) * 4;
                    *(float4*)&nY[row * 128 + c4] = py[q];
                }
            }
        }
        __syncthreads();                   // matvec done (sAt aliases sY0)

        // ---- stage hn^T into sAt ----
#pragma unroll
        for (int q = 0; q < 2; q++)
#pragma unroll
            for (int c = 0; c < 2; c++) {
                float2 f = unpk(macc[q][c]);
                int col = 2*cg + c;
                sAt[col*SA + 4*rg + 2*q]     = f.x;
                sAt[col*SA + 4*rg + 2*q + 1] = f.y;
            }
        __syncthreads();

        // ---- mlp1: [y | hn] @ W1 ; W2 chunk-0 prefetch hidden under it ----
        float4 pw0 = *(const float4*)&W2[w2k * 128 + w2c];  // chunk 0 (k 0..15)
        ull acc1[2][2];
        acc1[0][0]=acc1[0][1]=acc1[1][0]=acc1[1][1]=0ull;
#pragma unroll 8
        for (int k = 0; k < 128; k++)
            step4(acc1, &sYT[k*SA + 4*rg], &sW1[k*128 + 2*cg]);
#pragma unroll 8
        for (int k = 0; k < 128; k++)
            step4(acc1, &sAt[k*SA + 4*rg], &sW1[(128 + k)*128 + 2*cg]);
        __syncthreads();                   // all hn^T reads done (frees sY1 too)

        // ---- z = tanh(acc1 + b1) -> z^T into sAt; commit W2 chunk 0 ----
        *(float4*)&sW2h0[w2k * 128 + w2c] = pw0;
#pragma unroll
        for (int q = 0; q < 2; q++)
#pragma unroll
            for (int c = 0; c < 2; c++) {
                float2 f = unpk(acc1[q][c]);
                float bb = c ? b1v.y : b1v.x;
                int col = 2*cg + c;
                sAt[col*SA + 4*rg + 2*q]     = tanhf(f.x + bb);
                sAt[col*SA + 4*rg + 2*q + 1] = tanhf(f.y + bb);
            }
        __syncthreads();

        // ---- mlp2: k = z @ W2 + b2 ; W2 via smem chunk ping-pong ----
        ull acc2[2][2];
        acc2[0][0]=acc2[0][1]=acc2[1][0]=acc2[1][1]=0ull;
#pragma unroll 1
        for (int c8 = 0; c8 < 8; c8++) {
            const float* cur = (c8 & 1) ? sW2h1 : sW2h0;
            float* nxt = (c8 & 1) ? sW2h0 : sW2h1;
            float4 pw;
            if (c8 + 1 < 8)
                pw = *(const float4*)&W2[((c8+1)*16 + w2k) * 128 + w2c];
#pragma unroll
            for (int k = 0; k < 16; k++)
                step4(acc2, &sAt[(c8*16 + k)*SA + 4*rg], &cur[k*128 + 2*cg]);
            if (c8 + 1 < 8)
                *(float4*)&nxt[w2k * 128 + w2c] = pw;
            __syncthreads();
        }

        // ---- RK4 epilogue: yout first, publish, then sYT ----
        {
            const float wq = (s == 0 || s == 3) ? dt * (1.0f/6.0f) : dt * (1.0f/3.0f);
            const float cq = (s == 2) ? dt : 0.5f * dt;
            float yn[4][2];
#pragma unroll
            for (int q = 0; q < 2; q++)
#pragma unroll
                for (int c = 0; c < 2; c++) {
                    float2 f = unpk(acc2[q][c]);
                    float bb = c ? b2v.y : b2v.x;
                    float kv0 = f.x + bb, kv1 = f.y + bb;
                    int i0 = 2*q, i1 = 2*q + 1;
                    if (s == 0) { rk[i0][c] = hreg[i0][c] + wq * kv0;
                                  rk[i1][c] = hreg[i1][c] + wq * kv1; }
                    else        { rk[i0][c] += wq * kv0;
                                  rk[i1][c] += wq * kv1; }
                    if (s == 3) { hreg[i0][c] = rk[i0][c]; yn[i0][c] = rk[i0][c];
                                  hreg[i1][c] = rk[i1][c]; yn[i1][c] = rk[i1][c]; }
                    else        { yn[i0][c] = hreg[i0][c] + cq * kv0;
                                  yn[i1][c] = hreg[i1][c] + cq * kv1; }
                }
#pragma unroll
            for (int i = 0; i < 4; i++) {
                int idx = (r0 + 4*rg + i) * HH + 2*cg;
                float2 o = make_float2(yn[i][0], yn[i][1]);
                *(float2*)&yout[idx] = o;
                if (st == 15) *(float2*)&outp[idx] = o;
            }
            if (st < 15) {
                __syncthreads();           // all yout stores issued block-wide
                if (tid == 0) {
                    __threadfence();       // yout visible before flag
                    atomicExch(&g_done[blockIdx.x * 32], st + 1);
                }
                // refresh own y^T for next stage's mlp1
#pragma unroll
                for (int i = 0; i < 4; i++) {
                    int row = 4*rg + i;
                    sYT[(2*cg+0)*SA + row] = yn[i][0];
                    sYT[(2*cg+1)*SA + row] = yn[i][1];
                }
            }
        }
    }
}

// ---------------------------------------------------------------------------
extern "C" void kernel_launch(void* const* d_in, const int* in_sizes, int n_in,
                              void* d_out, int out_size)
{
    (void)in_sizes; (void)n_in; (void)out_size;
    const float* features = (const float*)d_in[0];
    const int*   spk      = (const int*)  d_in[1];
    const float* mmask    = (const float*)d_in[2];
    const float* Wp       = (const float*)d_in[3];
    const float* bp       = (const float*)d_in[4];
    const float* W1       = (const float*)d_in[5];
    const float* b1       = (const float*)d_in[6];
    const float* W2       = (const float*)d_in[7];
    const float* b2       = (const float*)d_in[8];
    float* out = (float*)d_out;

    static int attr_done = 0;
    if (!attr_done) {
        cudaFuncSetAttribute(ode_kernel,
                             cudaFuncAttributeMaxDynamicSharedMemorySize,
                             SMEM_BYTES);
        attr_done = 1;
    }

    build_band_kernel<<<NB, 384>>>(spk, mmask);
    proj_kernel<<<GRID, NT>>>(features, Wp, bp);
    ode_kernel<<<GRID, NT, SMEM_BYTES>>>(W1, b1, W2, b2, out);
}

// round 17
// speedup vs baseline: 1.0246x; 1.0246x over previous
#include <cuda_runtime.h>

// Problem constants
#define NB   4096
#define DIN  1856
#define HH   128
#define WB2  64        // truncated half-width (RK4-damped tail ~5e-6 end-to-end)
#define BSTR 384       // band row stride (t = d+191)
#define GRID 128       // persistent blocks, all co-resident
#define RPB  32        // rows per block
#define CH   48        // matvec chunk rows
#define NCH  4         // 4*48 = 192 window cols >= 2*64+32
#define NJW  (NCH*CH)  // 192
#define SA   36        // transposed-activation stride
#define NT   512       // threads per block

typedef unsigned long long ull;

// Persistent device scratch (zero-initialized at module load)
__device__ float g_band[NB * BSTR];
__device__ float g_h[NB * HH];
__device__ float g_ybuf[2][NB * HH];
__device__ int g_done[GRID];          // per-block stage flags (reset by proj)

// ---------------------------------------------------------------------------
// f32x2 packed-math helpers
// ---------------------------------------------------------------------------
__device__ __forceinline__ ull dup2(float x) {
    ull r; asm("mov.b64 %0, {%1, %1};" : "=l"(r) : "f"(x)); return r;
}
__device__ __forceinline__ void ffma2(ull& d, ull a, ull b) {
    asm("fma.rn.f32x2 %0, %1, %2, %0;" : "+l"(d) : "l"(a), "l"(b));
}
__device__ __forceinline__ float2 unpk(ull v) {
    float2 f; asm("mov.b64 {%0, %1}, %2;" : "=f"(f.x), "=f"(f.y) : "l"(v));
    return f;
}

// 4 rows x 2 cols microtile: 1 LDS.128 (row pairs, broadcast) + 1 LDS.64.
__device__ __forceinline__ void step4(ull acc[2][2],
                                      const float* __restrict__ aBase,
                                      const float* __restrict__ bBase)
{
    ulonglong2 a = *(const ulonglong2*)(aBase);        // rows (0,1),(2,3)
    float2 wv = *(const float2*)(bBase);
    ull w0 = dup2(wv.x), w1 = dup2(wv.y);
    ffma2(acc[0][0], a.x, w0); ffma2(acc[0][1], a.x, w1);
    ffma2(acc[1][0], a.y, w0); ffma2(acc[1][1], a.y, w1);
}
__device__ __forceinline__ void step4v(ull acc[2][2],
                                       const float* __restrict__ aBase,
                                       float2 wv)
{
    ulonglong2 a = *(const ulonglong2*)(aBase);
    ull w0 = dup2(wv.x), w1 = dup2(wv.y);
    ffma2(acc[0][0], a.x, w0); ffma2(acc[0][1], a.x, w1);
    ffma2(acc[1][0], a.y, w0); ffma2(acc[1][1], a.y, w1);
}

// ---------------------------------------------------------------------------
// Kernel 1: build normalized band adjacency (coalesced layout).
// Normalizer over the full 383-wide band (error vs full row ~7e-8).
// ---------------------------------------------------------------------------
__global__ void __launch_bounds__(384) build_band_kernel(
    const int* __restrict__ spk, const float* __restrict__ mmask)
{
    int i = blockIdx.x;
    int t = threadIdx.x;            // 0..383, d = t - 191
    int d = t - 191;
    int j = i + d;

    float val = 0.0f;
    bool valid = (t < 383 && j >= 0 && j < NB);
    if (valid) {
        if (d == 0) {
            val = 1.0f;
        } else {
            float temporal = expf(-0.1f * fabsf((float)d));
            if (spk[i] == spk[j]) {
                val = 0.8f * temporal;
            } else {
                float md = fabsf(mmask[i*3+0] - mmask[j*3+0])
                         + fabsf(mmask[i*3+1] - mmask[j*3+1])
                         + fabsf(mmask[i*3+2] - mmask[j*3+2]);
                float mod_sim = 1.0f - md * (1.0f/3.0f);
                val = 0.5f * temporal * mod_sim;
            }
        }
    }

    __shared__ float sd[384];
    sd[t] = val;
    __syncthreads();
    if (t < 128) sd[t] += sd[t + 256];
    __syncthreads();
    for (int s = 128; s > 0; s >>= 1) {
        if (t < s) sd[t] += sd[t + s];
        __syncthreads();
    }
    float inv = 1.0f / (sd[0] + 1e-8f);
    g_band[i * BSTR + t] = val * inv;
}

// ---------------------------------------------------------------------------
// Kernel 2: projection h0 = X @ Wp + bp.  Also resets g_done for this launch.
// ---------------------------------------------------------------------------
__global__ void __launch_bounds__(NT) proj_kernel(
    const float* __restrict__ X, const float* __restrict__ Wp,
    const float* __restrict__ bp)
{
    if (threadIdx.x == 0) g_done[blockIdx.x] = 0;     // flag reset (per launch)

    __shared__ __align__(16) float As[32 * SA];
    __shared__ __align__(16) float Bs[32 * 128];
    const int m0  = blockIdx.x * RPB;
    const int tid = threadIdx.x;
    const int rg  = tid >> 6;        // rows 4rg..4rg+3 (warp-uniform)
    const int cg  = tid & 63;        // cols 2cg, 2cg+1

    ull acc[2][2];
    acc[0][0]=acc[0][1]=acc[1][0]=acc[1][1]=0ull;

    const int ar  = tid >> 4;        // 0..31
    const int ak2 = (tid & 15) * 2;  // 0..30

    for (int k0 = 0; k0 < DIN; k0 += 32) {
        {
            float2 v = *(const float2*)&X[(m0 + ar) * DIN + k0 + ak2];
            As[(ak2+0)*SA + ar] = v.x;
            As[(ak2+1)*SA + ar] = v.y;
        }
#pragma unroll
        for (int i = tid; i < 1024; i += NT) {
            int k = i >> 5, c4 = (i & 31) * 4;
            *(float4*)&Bs[k*128 + c4] = *(const float4*)&Wp[(k0 + k) * HH + c4];
        }
        __syncthreads();
#pragma unroll 8
        for (int k = 0; k < 32; k++)
            step4(acc, &As[k*SA + 4*rg], &Bs[k*128 + 2*cg]);
        __syncthreads();
    }

    float2 bb = *(const float2*)&bp[2*cg];
#pragma unroll
    for (int q = 0; q < 2; q++) {
        float2 f0 = unpk(acc[q][0]);
        float2 f1 = unpk(acc[q][1]);
        int r_even = m0 + 4*rg + 2*q;
        float2 o0 = make_float2(f0.x + bb.x, f1.x + bb.y);
        float2 o1 = make_float2(f0.y + bb.x, f1.y + bb.y);
        *(float2*)&g_h[r_even * HH + 2*cg]           = o0;
        *(float2*)&g_ybuf[0][r_even * HH + 2*cg]     = o0;
        *(float2*)&g_h[(r_even+1) * HH + 2*cg]       = o1;
        *(float2*)&g_ybuf[0][(r_even+1) * HH + 2*cg] = o1;
    }
}

// ---------------------------------------------------------------------------
// Kernel 3: persistent ODE kernel (R15 architecture, WB2=64 window).
// Band slice resident in smem for all 16 stages (stage-invariant).
// Neighbor-only dataflow sync, y-only double-buffered staging,
// W1 resident in smem, W2 via 8-deep register prefetch.
// ---------------------------------------------------------------------------
#define SW1_FLOATS (256 * 128)             // 32768
#define SY_FLOATS  (CH * 128)              // 6144
#define SBT_FLOATS (NJW * 32)              // 6144
#define SYT_FLOATS (128 * SA)              // 4608
#define SMEM_FLOATS (SW1_FLOATS + 2*SY_FLOATS + SBT_FLOATS + SYT_FLOATS)
#define SMEM_BYTES  (SMEM_FLOATS * 4)      // 223232 B (fits 232448 cap)

__global__ void __launch_bounds__(NT, 1) ode_kernel(
    const float* __restrict__ W1, const float* __restrict__ b1,
    const float* __restrict__ W2, const float* __restrict__ b2,
    float* __restrict__ outp)
{
    extern __shared__ __align__(16) float smem[];
    float* sW1 = smem;                     // [256][128]
    float* sY0 = sW1 + SW1_FLOATS;         // [CH][128] buffer 0
    float* sY1 = sY0 + SY_FLOATS;          // [CH][128] buffer 1
    float* sBT = sY1 + SY_FLOATS;          // [NJW][32] resident band slice
    float* sYT = sBT + SBT_FLOATS;         // [128][SA] y^T own rows (persistent)
    float* sAt = sY0;                      // [128][SA] hn^T / z^T (aliases sY0)

    const int tid = threadIdx.x;
    const int rg  = tid >> 6;              // warp-uniform, rows 4rg..4rg+3
    const int cg  = tid & 63;              // cols 2cg, 2cg+1
    const int r0  = blockIdx.x * RPB;
    const int jbase = r0 - WB2;

    // one-time staging: W1, band slice (transposed [jj][r]), y0^T
#pragma unroll
    for (int i = tid; i < SW1_FLOATS/4; i += NT)
        *(float4*)&sW1[i*4] = *(const float4*)&W1[i*4];
#pragma unroll
    for (int i = tid; i < SBT_FLOATS; i += NT) {
        int jj = i >> 5, r = i & 31;
        int gj = jbase + jj;
        float bv = 0.0f;
        if ((unsigned)gj < (unsigned)NB) {
            int dd = jj + 127 - r;         // in [96, 318] always
            bv = g_band[(r0 + r) * BSTR + dd];
        }
        sBT[i] = bv;
    }
#pragma unroll
    for (int i = tid; i < 4096; i += NT) {
        int r = i >> 7, c = i & 127;
        sYT[c*SA + r] = g_ybuf[0][(r0 + r) * HH + c];
    }

    // persistent register state: rows 4rg..4rg+3, cols 2cg, 2cg+1
    float hreg[4][2], rk[4][2];
#pragma unroll
    for (int i = 0; i < 4; i++) {
        float2 v = *(const float2*)&g_h[(r0 + 4*rg + i) * HH + 2*cg];
        hreg[i][0] = v.x; hreg[i][1] = v.y;
    }
    float2 b1v = *(const float2*)&b1[2*cg];
    float2 b2v = *(const float2*)&b2[2*cg];
    const float dt = 0.25f;
    __syncthreads();

#pragma unroll 1
    for (int st = 0; st < 16; st++) {
        const int s = st & 3;
        const float* __restrict__ yin  = g_ybuf[st & 1];
        float* __restrict__       yout = g_ybuf[(st + 1) & 1];

        // ---- neighbor dataflow sync: wait for blocks +-2 to publish yin ----
        // (window spans [r0-64, r0+128) -> rows from blocks -2..+3; use +-3
        //  conservatively to cover the +128 edge.)
        if (st > 0) {
            if (tid < 7) {
                int nb = (int)blockIdx.x - 3 + tid;
                if (nb >= 0 && nb < GRID) {
                    while (((volatile int*)g_done)[nb] < st) { }
                }
            }
            __syncthreads();
            __threadfence();
        }

        // ---- banded matvec: y double-buffered, band resident ----
        ull macc[2][2];
        macc[0][0]=macc[0][1]=macc[1][0]=macc[1][1]=0ull;

        float4 py[3];

        // prefetch + commit chunk 0 into buffer 0
        {
#pragma unroll
            for (int q = 0; q < 3; q++) {
                int i = tid + q*NT;
                int row = i >> 5, c4 = (i & 31) * 4;
                int gj = jbase + row;
                py[q] = make_float4(0.f,0.f,0.f,0.f);
                if ((unsigned)gj < (unsigned)NB)
                    py[q] = __ldcg((const float4*)&yin[gj * HH + c4]);
                *(float4*)&sY0[row * 128 + c4] = py[q];
            }
        }

#pragma unroll 1
        for (int ch = 0; ch < NCH; ch++) {
            __syncthreads();               // current buffer ready
            const float* cY = (ch & 1) ? sY1 : sY0;
            float* nY = (ch & 1) ? sY0 : sY1;
            const float* cB = &sBT[ch * CH * 32];

            // issue next chunk's y loads (latency overlapped with compute)
            if (ch + 1 < NCH) {
                const int j0 = jbase + (ch + 1) * CH;
#pragma unroll
                for (int q = 0; q < 3; q++) {
                    int i = tid + q*NT;
                    int row = i >> 5, c4 = (i & 31) * 4;
                    int gj = j0 + row;
                    py[q] = make_float4(0.f,0.f,0.f,0.f);
                    if ((unsigned)gj < (unsigned)NB)
                        py[q] = __ldcg((const float4*)&yin[gj * HH + c4]);
                }
            }

#pragma unroll 8
            for (int j = 0; j < CH; j++)
                step4(macc, &cB[j*32 + 4*rg], &cY[j*128 + 2*cg]);

            // commit prefetched chunk to the other buffer
            if (ch + 1 < NCH) {
#pragma unroll
                for (int q = 0; q < 3; q++) {
                    int i = tid + q*NT;
                    int row = i >> 5, c4 = (i & 31) * 4;
                    *(float4*)&nY[row * 128 + c4] = py[q];
                }
            }
        }
        __syncthreads();                   // all matvec compute done (sAt aliases sY0)

        // ---- stage hn^T into sAt ----
#pragma unroll
        for (int q = 0; q < 2; q++)
#pragma unroll
            for (int c = 0; c < 2; c++) {
                float2 f = unpk(macc[q][c]);
                int col = 2*cg + c;
                sAt[col*SA + 4*rg + 2*q]     = f.x;
                sAt[col*SA + 4*rg + 2*q + 1] = f.y;
            }
        __syncthreads();

        // ---- mlp1: [y | hn] @ W1 ----
        ull acc1[2][2];
        acc1[0][0]=acc1[0][1]=acc1[1][0]=acc1[1][1]=0ull;
#pragma unroll 8
        for (int k = 0; k < 128; k++)
            step4(acc1, &sYT[k*SA + 4*rg], &sW1[k*128 + 2*cg]);
#pragma unroll 8
        for (int k = 0; k < 128; k++)
            step4(acc1, &sAt[k*SA + 4*rg], &sW1[(128 + k)*128 + 2*cg]);
        __syncthreads();                   // all hn^T reads done

        // ---- z = tanh(acc1 + b1) -> z^T into sAt ----
#pragma unroll
        for (int q = 0; q < 2; q++)
#pragma unroll
            for (int c = 0; c < 2; c++) {
                float2 f = unpk(acc1[q][c]);
                float bb = c ? b1v.y : b1v.x;
                int col = 2*cg + c;
                sAt[col*SA + 4*rg + 2*q]     = tanhf(f.x + bb);
                sAt[col*SA + 4*rg + 2*q + 1] = tanhf(f.y + bb);
            }
        __syncthreads();

        // ---- mlp2: k = z @ W2 + b2  (W2 via 8-deep register prefetch) ----
        ull acc2[2][2];
        acc2[0][0]=acc2[0][1]=acc2[1][0]=acc2[1][1]=0ull;
#pragma unroll 1
        for (int g = 0; g < 16; g++) {
            float2 w[8];
#pragma unroll
            for (int j = 0; j < 8; j++)
                w[j] = *(const float2*)&W2[(g*8 + j)*128 + 2*cg];
#pragma unroll
            for (int j = 0; j < 8; j++)
                step4v(acc2, &sAt[(g*8 + j)*SA + 4*rg], w[j]);
        }

        // ---- RK4 epilogue ----
        {
            const float wq = (s == 0 || s == 3) ? dt * (1.0f/6.0f) : dt * (1.0f/3.0f);
            const float cq = (s == 2) ? dt : 0.5f * dt;
            float kvals[4][2];
#pragma unroll
            for (int q = 0; q < 2; q++)
#pragma unroll
                for (int c = 0; c < 2; c++) {
                    float2 f = unpk(acc2[q][c]);
                    float bb = c ? b2v.y : b2v.x;
                    kvals[2*q][c]   = f.x + bb;
                    kvals[2*q+1][c] = f.y + bb;
                }
            float yn[4][2];
#pragma unroll
            for (int i = 0; i < 4; i++)
#pragma unroll
                for (int c = 0; c < 2; c++) {
                    float kv = kvals[i][c];
                    if (s == 0) rk[i][c] = hreg[i][c] + wq * kv;
                    else        rk[i][c] += wq * kv;
                    if (s == 3) { hreg[i][c] = rk[i][c]; yn[i][c] = rk[i][c]; }
                    else        yn[i][c] = hreg[i][c] + cq * kv;
                }
#pragma unroll
            for (int i = 0; i < 4; i++) {
                int row = 4*rg + i;
                int idx = (r0 + row) * HH + 2*cg;
                float2 o = make_float2(yn[i][0], yn[i][1]);
                *(float2*)&yout[idx] = o;
                sYT[(2*cg+0)*SA + row] = yn[i][0];
                sYT[(2*cg+1)*SA + row] = yn[i][1];
                if (st == 15) *(float2*)&outp[idx] = o;
            }
        }

        // ---- publish stage completion for neighbors ----
        if (st < 15) {
            __syncthreads();               // all yout stores issued block-wide
            if (tid == 0) {
                __threadfence();           // yout visible before flag
                atomicExch(&g_done[blockIdx.x], st + 1);
            }
        }
    }
}

// ---------------------------------------------------------------------------
extern "C" void kernel_launch(void* const* d_in, const int* in_sizes, int n_in,
                              void* d_out, int out_size)
{
    (void)in_sizes; (void)n_in; (void)out_size;
    const float* features = (const float*)d_in[0];
    const int*   spk      = (const int*)  d_in[1];
    const float* mmask    = (const float*)d_in[2];
    const float* Wp       = (const float*)d_in[3];
    const float* bp       = (const float*)d_in[4];
    const float* W1       = (const float*)d_in[5];
    const float* b1       = (const float*)d_in[6];
    const float* W2       = (const float*)d_in[7];
    const float* b2       = (const float*)d_in[8];
    float* out = (float*)d_out;

    static int attr_done = 0;
    if (!attr_done) {
        cudaFuncSetAttribute(ode_kernel,
                             cudaFuncAttributeMaxDynamicSharedMemorySize,
                             SMEM_BYTES);
        attr_done = 1;
    }

    build_band_kernel<<<NB, 384>>>(spk, mmask);
    proj_kernel<<<GRID, NT>>>(features, Wp, bp);
    ode_kernel<<<GRID, NT, SMEM_BYTES>>>(W1, b1, W2, b2, out);
}